// round 5
// baseline (speedup 1.0000x reference)
#include <cuda_runtime.h>
#include <cstdint>

#define BATCH 2
#define CCH   128
#define NSEQ  8192
#define MSEL  2048

// ---------------- scratch (static device globals; no allocation) ----------------
__device__ float g_qT[(size_t)BATCH * NSEQ * CCH];       // [b][n][c]
__device__ float g_kT[(size_t)BATCH * NSEQ * CCH];       // [b][m][c]
__device__ float g_v [(size_t)BATCH * CCH * NSEQ];       // [b][c][n]
__device__ float g_att[(size_t)BATCH * NSEQ * NSEQ];     // logits, then attention [b][n][m]
__device__ float g_sel[BATCH * NSEQ];                    // selection (XLA-order col sums)
__device__ int   g_idx[BATCH * MSEL];

// ---------------- K1: q,k,v projections (ascending-c fma chains == cublas) ----------------
__global__ __launch_bounds__(256) void qkv_kernel(const float* __restrict__ x,
                                                  const float* __restrict__ Wq,
                                                  const float* __restrict__ Wk,
                                                  const float* __restrict__ Wv) {
    __shared__ float xs[CCH][64];
    const int b  = blockIdx.y;
    const int n0 = blockIdx.x * 64;
    const float* xb = x + (size_t)b * CCH * NSEQ;

    for (int e4 = threadIdx.x; e4 < CCH * 16; e4 += 256) {
        int ci = e4 >> 4, k4 = e4 & 15;
        float4 v = *reinterpret_cast<const float4*>(xb + (size_t)ci * NSEQ + n0 + k4 * 4);
        xs[ci][k4 * 4 + 0] = v.x; xs[ci][k4 * 4 + 1] = v.y;
        xs[ci][k4 * 4 + 2] = v.z; xs[ci][k4 * 4 + 3] = v.w;
    }
    __syncthreads();

    for (int o = threadIdx.x; o < CCH * 64; o += 256) {
        int co = o >> 6, n = o & 63;
        const float* wq = Wq + co * CCH;
        const float* wk = Wk + co * CCH;
        const float* wv = Wv + co * CCH;
        float aq = 0.f, ak = 0.f, av = 0.f;
#pragma unroll 8
        for (int ci = 0; ci < CCH; ci++) {      // strict ascending-c chain
            float xv = xs[ci][n];
            aq = fmaf(wq[ci], xv, aq);
            ak = fmaf(wk[ci], xv, ak);
            av = fmaf(wv[ci], xv, av);
        }
        g_v[((size_t)b * CCH + co) * NSEQ + n0 + n] = av;
        size_t tr = ((size_t)b * NSEQ + n0 + n) * CCH + co;
        g_qT[tr] = aq;
        g_kT[tr] = ak;
    }
}

// ---------------- K2: energy GEMM (logits = q^T k / sqrt(C)), ascending-k chains ----------------
#define K2_SMEM (2 * 128 * 132 * 4)
__global__ __launch_bounds__(256, 1) void energy_kernel() {
    extern __shared__ float sm[];
    float* As = sm;               // [128][132]
    float* Bs = sm + 128 * 132;   // [128][132]
    const int b  = blockIdx.z;
    const int n0 = blockIdx.y * 128;
    const int m0 = blockIdx.x * 128;
    const int tid = threadIdx.x;

    const float* Ag = g_qT + ((size_t)b * NSEQ + n0) * CCH;
    const float* Bg = g_kT + ((size_t)b * NSEQ + m0) * CCH;
    for (int e4 = tid; e4 < 128 * 32; e4 += 256) {
        int r = e4 >> 5, c4 = e4 & 31;
        float4 va = *reinterpret_cast<const float4*>(Ag + r * CCH + c4 * 4);
        float4 vb = *reinterpret_cast<const float4*>(Bg + r * CCH + c4 * 4);
        *reinterpret_cast<float4*>(&As[r * 132 + c4 * 4]) = va;
        *reinterpret_cast<float4*>(&Bs[r * 132 + c4 * 4]) = vb;
    }
    __syncthreads();

    const int tx = tid & 15, ty = tid >> 4;
    float acc[8][8];
#pragma unroll
    for (int i = 0; i < 8; i++)
#pragma unroll
        for (int j = 0; j < 8; j++) acc[i][j] = 0.f;

#pragma unroll 4
    for (int k = 0; k < 128; k += 4) {
        float4 a[8], bb[8];
#pragma unroll
        for (int i = 0; i < 8; i++) a[i]  = *reinterpret_cast<float4*>(&As[(ty + 16 * i) * 132 + k]);
#pragma unroll
        for (int j = 0; j < 8; j++) bb[j] = *reinterpret_cast<float4*>(&Bs[(tx + 16 * j) * 132 + k]);
#pragma unroll
        for (int i = 0; i < 8; i++)
#pragma unroll
            for (int j = 0; j < 8; j++) {       // per-acc chain is ascending k
                acc[i][j] = fmaf(a[i].x, bb[j].x, acc[i][j]);
                acc[i][j] = fmaf(a[i].y, bb[j].y, acc[i][j]);
                acc[i][j] = fmaf(a[i].z, bb[j].z, acc[i][j]);
                acc[i][j] = fmaf(a[i].w, bb[j].w, acc[i][j]);
            }
    }

    const float sc = sqrtf(128.0f);   // exact same f32 constant jax's sqrt produces
    float* out = g_att + ((size_t)b * NSEQ + n0) * NSEQ + m0;
#pragma unroll
    for (int i = 0; i < 8; i++)
#pragma unroll
        for (int j = 0; j < 8; j++)
            out[(size_t)(ty + 16 * i) * NSEQ + tx + 16 * j] = __fdiv_rn(acc[i][j], sc);
}

// ---------------- K3: softmax rows in place (logits -> attention, f32) ----------------
__global__ __launch_bounds__(256) void softmax_kernel() {
    __shared__ float rowbuf[NSEQ];   // 32KB
    __shared__ float  redf[8];
    __shared__ double redd[8];
    __shared__ float  s_rmax, s_S;

    const int b   = blockIdx.y;
    const int r0  = blockIdx.x * 128;
    const int tid = threadIdx.x;
    const int lane = tid & 31, wid = tid >> 5;

    for (int rr = 0; rr < 128; rr++) {
        const int row = r0 + rr;
        float* L = g_att + ((size_t)b * NSEQ + row) * NSEQ;

        float lmax = -3.0e38f;
        for (int e4 = tid; e4 < NSEQ / 4; e4 += 256) {
            float4 v = *reinterpret_cast<const float4*>(L + e4 * 4);
            *reinterpret_cast<float4*>(&rowbuf[e4 * 4]) = v;
            lmax = fmaxf(lmax, fmaxf(fmaxf(v.x, v.y), fmaxf(v.z, v.w)));
        }
#pragma unroll
        for (int o = 16; o; o >>= 1) lmax = fmaxf(lmax, __shfl_xor_sync(0xffffffffu, lmax, o));
        if (lane == 0) redf[wid] = lmax;
        __syncthreads();
        if (tid == 0) {
            float m = redf[0];
#pragma unroll
            for (int w = 1; w < 8; w++) m = fmaxf(m, redf[w]);
            s_rmax = m;
        }
        __syncthreads();
        const float rm = s_rmax;

        // exp (libdevice expf == XLA's f32 exp lowering) + fp64 row sum
        double lsum = 0.0;
        for (int e4 = tid; e4 < NSEQ / 4; e4 += 256) {
            float4 v = *reinterpret_cast<float4*>(&rowbuf[e4 * 4]);
            v.x = expf(v.x - rm); v.y = expf(v.y - rm);
            v.z = expf(v.z - rm); v.w = expf(v.w - rm);
            *reinterpret_cast<float4*>(&rowbuf[e4 * 4]) = v;
            lsum += (double)v.x + (double)v.y + (double)v.z + (double)v.w;
        }
#pragma unroll
        for (int o = 16; o; o >>= 1) lsum += __shfl_xor_sync(0xffffffffu, lsum, o);
        if (lane == 0) redd[wid] = lsum;
        __syncthreads();
        if (tid == 0) {
            double s = redd[0];
#pragma unroll
            for (int w = 1; w < 8; w++) s += redd[w];
            s_S = (float)s;
        }
        __syncthreads();
        const float Sf = s_S;

        for (int e4 = tid; e4 < NSEQ / 4; e4 += 256) {
            float4 p = *reinterpret_cast<float4*>(&rowbuf[e4 * 4]);
            p.x = __fdiv_rn(p.x, Sf); p.y = __fdiv_rn(p.y, Sf);
            p.z = __fdiv_rn(p.z, Sf); p.w = __fdiv_rn(p.w, Sf);
            *reinterpret_cast<float4*>(L + e4 * 4) = p;
        }
        __syncthreads();
    }
}

// ---------------- K3b: XLA-GPU two-stage column reduction replica ----------------
// GpuTreeReductionRewriter: extent 8192 > WarpSize^2 -> reshape [8, 1024],
// stage1 reduces inner 1024 (per-thread strided-32 chain of 32 adds, k ascending,
// then 32-lane shfl_down tree 16,8,4,2,1); stage2 reduces the 8 partials via the
// same warp tree with lanes 8..31 = init 0, which collapses to
// ((s0+s4)+(s2+s6)) + ((s1+s5)+(s3+s7)).
__global__ __launch_bounds__(1024) void colsum_kernel() {
    __shared__ float part[32][33];
    const int b  = blockIdx.y;
    const int m  = blockIdx.x * 32 + threadIdx.x;
    const int ty = threadIdx.y;
    const float* A = g_att + (size_t)b * NSEQ * NSEQ + m;

    // stage-1 per-thread chains: s[p] = sum_{k=0..31} a[p*1024 + ty + 32k][m]
    float s[8];
#pragma unroll
    for (int p = 0; p < 8; p++) {
        float acc = 0.f;
#pragma unroll
        for (int k = 0; k < 32; k++)
            acc += A[(size_t)(p * 1024 + ty + 32 * k) * NSEQ];
        s[p] = acc;
    }

    // stage-1 warp trees (one per p), via smem transpose so lanes hold the 32 partials
    float s1[8];
#pragma unroll
    for (int p = 0; p < 8; p++) {
        __syncthreads();
        part[ty][threadIdx.x] = s[p];
        __syncthreads();
        float q = part[threadIdx.x][ty];   // lane tx holds partial_{y=tx} of column (bx*32+ty)
#pragma unroll
        for (int off = 16; off; off >>= 1)
            q += __shfl_down_sync(0xffffffffu, q, off);
        s1[p] = q;                          // valid on lane tx == 0
    }

    if (threadIdx.x == 0) {
        float r = ((s1[0] + s1[4]) + (s1[2] + s1[6]))
                + ((s1[1] + s1[5]) + (s1[3] + s1[7]));
        g_sel[b * NSEQ + blockIdx.x * 32 + ty] = r;
    }
}

// ---------------- K4: top-k (bitonic sort, desc value / asc index tie-break) ----------------
#define K4_SMEM (NSEQ * 8)
__global__ __launch_bounds__(1024) void topk_kernel() {
    extern __shared__ unsigned long long keys[];
    const int b = blockIdx.x;
    const int tid = threadIdx.x;

    for (int e = tid; e < NSEQ; e += 1024) {
        unsigned int u = __float_as_uint(g_sel[b * NSEQ + e]);
        u = (u & 0x80000000u) ? ~u : (u | 0x80000000u);  // order-preserving map
        u = ~u;                                           // descending by value
        keys[e] = ((unsigned long long)u << 32) | (unsigned int)e;  // ties -> ascending index
    }
    __syncthreads();

    for (int size = 2; size <= NSEQ; size <<= 1) {
        for (int stride = size >> 1; stride > 0; stride >>= 1) {
            for (int i = tid; i < NSEQ; i += 1024) {
                int j = i ^ stride;
                if (j > i) {
                    bool up = ((i & size) == 0);
                    unsigned long long a = keys[i], c = keys[j];
                    if ((a > c) == up) { keys[i] = c; keys[j] = a; }
                }
            }
            __syncthreads();
        }
    }

    for (int e = tid; e < MSEL; e += 1024)
        g_idx[b * MSEL + e] = (int)(keys[e] & 0xffffffffu);
}

// ---------------- K5: gather attention rows + scores @ v^T ----------------
__global__ __launch_bounds__(256) void out_kernel(float* __restrict__ out) {
    __shared__ float Vs[64][36];   // [c][k]
    __shared__ float Ps[64][36];   // [j][k]
    __shared__ int   srow[64];

    const int b  = blockIdx.z;
    const int c0 = blockIdx.y * 64;
    const int j0 = blockIdx.x * 64;
    const int tid = threadIdx.x;
    const int tx = tid & 15, ty = tid >> 4;

    if (tid < 64) srow[tid] = g_idx[b * MSEL + j0 + tid];
    __syncthreads();

    float acc[4][4];
#pragma unroll
    for (int i = 0; i < 4; i++)
#pragma unroll
        for (int j = 0; j < 4; j++) acc[i][j] = 0.f;

    const float* vb = g_v + ((size_t)b * CCH + c0) * NSEQ;
    const float* Ab = g_att + (size_t)b * NSEQ * NSEQ;

    for (int k0 = 0; k0 < NSEQ; k0 += 32) {
#pragma unroll
        for (int e4 = tid; e4 < 512; e4 += 256) {
            int r = e4 >> 3, k4 = e4 & 7;
            float4 v = *reinterpret_cast<const float4*>(vb + (size_t)r * NSEQ + k0 + k4 * 4);
            *reinterpret_cast<float4*>(&Vs[r][k4 * 4]) = v;
            float4 l = *reinterpret_cast<const float4*>(Ab + (size_t)srow[r] * NSEQ + k0 + k4 * 4);
            *reinterpret_cast<float4*>(&Ps[r][k4 * 4]) = l;
        }
        __syncthreads();
#pragma unroll
        for (int k = 0; k < 32; k += 4) {
            float4 a[4], p[4];
#pragma unroll
            for (int i = 0; i < 4; i++) a[i] = *reinterpret_cast<float4*>(&Vs[ty + 16 * i][k]);
#pragma unroll
            for (int j = 0; j < 4; j++) p[j] = *reinterpret_cast<float4*>(&Ps[tx + 16 * j][k]);
#pragma unroll
            for (int i = 0; i < 4; i++)
#pragma unroll
                for (int j = 0; j < 4; j++) {
                    acc[i][j] = fmaf(a[i].x, p[j].x, acc[i][j]);
                    acc[i][j] = fmaf(a[i].y, p[j].y, acc[i][j]);
                    acc[i][j] = fmaf(a[i].z, p[j].z, acc[i][j]);
                    acc[i][j] = fmaf(a[i].w, p[j].w, acc[i][j]);
                }
        }
        __syncthreads();
    }

#pragma unroll
    for (int i = 0; i < 4; i++)
#pragma unroll
        for (int j = 0; j < 4; j++)
            out[((size_t)b * CCH + c0 + ty + 16 * i) * MSEL + j0 + tx + 16 * j] = acc[i][j];
}

// ---------------- launch ----------------
extern "C" void kernel_launch(void* const* d_in, const int* in_sizes, int n_in,
                              void* d_out, int out_size) {
    const float* x  = (const float*)d_in[0];
    const float* Wq = (const float*)d_in[1];
    const float* Wk = (const float*)d_in[2];
    const float* Wv = (const float*)d_in[3];
    float* out = (float*)d_out;

    cudaFuncSetAttribute(energy_kernel, cudaFuncAttributeMaxDynamicSharedMemorySize, K2_SMEM);
    cudaFuncSetAttribute(topk_kernel,   cudaFuncAttributeMaxDynamicSharedMemorySize, K4_SMEM);

    qkv_kernel<<<dim3(NSEQ / 64, BATCH), 256>>>(x, Wq, Wk, Wv);
    energy_kernel<<<dim3(NSEQ / 128, NSEQ / 128, BATCH), 256, K2_SMEM>>>();
    softmax_kernel<<<dim3(64, BATCH), 256>>>();
    colsum_kernel<<<dim3(NSEQ / 32, BATCH), dim3(32, 32)>>>();
    topk_kernel<<<BATCH, 1024, K4_SMEM>>>();
    out_kernel<<<dim3(MSEL / 64, CCH / 64, BATCH), 256>>>(out);
}

// round 6
// speedup vs baseline: 1.0631x; 1.0631x over previous
#include <cuda_runtime.h>
#include <cstdint>

#define BATCH 2
#define CCH   128
#define NSEQ  8192
#define MSEL  2048

// ---------------- f32x2 packed helpers (sm_103a FFMA2 — PTX only) ----------------
__device__ __forceinline__ unsigned long long pack2(float lo, float hi) {
    unsigned long long r;
    asm("mov.b64 %0, {%1,%2};" : "=l"(r) : "f"(lo), "f"(hi));
    return r;
}
__device__ __forceinline__ void unpack2(unsigned long long v, float& lo, float& hi) {
    asm("mov.b64 {%0,%1}, %2;" : "=f"(lo), "=f"(hi) : "l"(v));
}
// d = a*b + d, elementwise IEEE f32 RN per component (bit-identical to 2x fmaf)
__device__ __forceinline__ void fma2(unsigned long long& d, unsigned long long a, unsigned long long b) {
    asm("fma.rn.f32x2 %0, %1, %2, %0;" : "+l"(d) : "l"(a), "l"(b));
}

// ---------------- scratch (static device globals; no allocation) ----------------
__device__ float g_qT[(size_t)BATCH * NSEQ * CCH];       // [b][n][c]
__device__ float g_kT[(size_t)BATCH * NSEQ * CCH];       // [b][m][c]
__device__ float g_v [(size_t)BATCH * CCH * NSEQ];       // [b][c][n]
__device__ float g_att[(size_t)BATCH * NSEQ * NSEQ];     // logits, then attention [b][n][m]
__device__ float g_sel[BATCH * NSEQ];                    // selection (XLA-order col sums)
__device__ int   g_idx[BATCH * MSEL];

// ---------------- K1: q,k,v projections (ascending-c fma chains) ----------------
__global__ __launch_bounds__(256) void qkv_kernel(const float* __restrict__ x,
                                                  const float* __restrict__ Wq,
                                                  const float* __restrict__ Wk,
                                                  const float* __restrict__ Wv) {
    __shared__ float xs[CCH][64];
    const int b  = blockIdx.y;
    const int n0 = blockIdx.x * 64;
    const float* xb = x + (size_t)b * CCH * NSEQ;

    for (int e4 = threadIdx.x; e4 < CCH * 16; e4 += 256) {
        int ci = e4 >> 4, k4 = e4 & 15;
        float4 v = *reinterpret_cast<const float4*>(xb + (size_t)ci * NSEQ + n0 + k4 * 4);
        xs[ci][k4 * 4 + 0] = v.x; xs[ci][k4 * 4 + 1] = v.y;
        xs[ci][k4 * 4 + 2] = v.z; xs[ci][k4 * 4 + 3] = v.w;
    }
    __syncthreads();

    for (int o = threadIdx.x; o < CCH * 64; o += 256) {
        int co = o >> 6, n = o & 63;
        const float* wq = Wq + co * CCH;
        const float* wk = Wk + co * CCH;
        const float* wv = Wv + co * CCH;
        float aq = 0.f, ak = 0.f, av = 0.f;
#pragma unroll 8
        for (int ci = 0; ci < CCH; ci++) {      // strict ascending-c chain
            float xv = xs[ci][n];
            aq = fmaf(wq[ci], xv, aq);
            ak = fmaf(wk[ci], xv, ak);
            av = fmaf(wv[ci], xv, av);
        }
        g_v[((size_t)b * CCH + co) * NSEQ + n0 + n] = av;
        size_t tr = ((size_t)b * NSEQ + n0 + n) * CCH + co;
        g_qT[tr] = aq;
        g_kT[tr] = ak;
    }
}

// ---------------- K2: energy GEMM with packed FFMA2 ----------------
// A tile stored in smem as row-pairs: As_p[r][k] = (A[r][k], A[r+64][k]), r<64.
// Each f32x2 accumulator component keeps its own ascending-k fma chain ->
// logits bit-identical to the scalar version.
#define AS_STRIDE 260                        // floats per packed row (2*128 + 4 pad)
#define K2_SMEM ((64 * AS_STRIDE + 128 * 132) * 4)
__global__ __launch_bounds__(256, 1) void energy_kernel() {
    extern __shared__ float sm[];
    float* As = sm;                          // packed pairs [64][AS_STRIDE]
    float* Bs = sm + 64 * AS_STRIDE;         // row-major [128][132]
    const int b  = blockIdx.z;
    const int n0 = blockIdx.y * 128;
    const int m0 = blockIdx.x * 128;
    const int tid = threadIdx.x;

    const float* Ag = g_qT + ((size_t)b * NSEQ + n0) * CCH;
    const float* Bg = g_kT + ((size_t)b * NSEQ + m0) * CCH;
    for (int e4 = tid; e4 < 128 * 32; e4 += 256) {
        int r = e4 >> 5, c4 = e4 & 31;
        float4 va = *reinterpret_cast<const float4*>(Ag + r * CCH + c4 * 4);
        float4 vb = *reinterpret_cast<const float4*>(Bg + r * CCH + c4 * 4);
        float* ap = As + (r & 63) * AS_STRIDE + (r >> 6);
        ap[(c4 * 4 + 0) * 2] = va.x; ap[(c4 * 4 + 1) * 2] = va.y;
        ap[(c4 * 4 + 2) * 2] = va.z; ap[(c4 * 4 + 3) * 2] = va.w;
        *reinterpret_cast<float4*>(&Bs[r * 132 + c4 * 4]) = vb;
    }
    __syncthreads();

    const int tx = tid & 15, ty = tid >> 4;
    unsigned long long acc2[4][8];
#pragma unroll
    for (int i = 0; i < 4; i++)
#pragma unroll
        for (int j = 0; j < 8; j++) acc2[i][j] = 0ull;

#pragma unroll 2
    for (int k = 0; k < 128; k += 4) {
        // packed A operands: a2[i2][s] covers k+2s, k+2s+1 (pairs of rows r, r+64)
        float4 av[4][2];
#pragma unroll
        for (int i2 = 0; i2 < 4; i2++) {
            const float4* ap = reinterpret_cast<const float4*>(As + (ty + 16 * i2) * AS_STRIDE + 2 * k);
            av[i2][0] = ap[0];
            av[i2][1] = ap[1];
        }
#pragma unroll
        for (int j = 0; j < 8; j++) {
            float4 bv = *reinterpret_cast<const float4*>(&Bs[(tx + 16 * j) * 132 + k]);
            unsigned long long b0 = pack2(bv.x, bv.x);
            unsigned long long b1 = pack2(bv.y, bv.y);
            unsigned long long b2 = pack2(bv.z, bv.z);
            unsigned long long b3 = pack2(bv.w, bv.w);
#pragma unroll
            for (int i2 = 0; i2 < 4; i2++) {
                const unsigned long long* a = reinterpret_cast<const unsigned long long*>(&av[i2][0]);
                fma2(acc2[i2][j], a[0], b0);   // k
                fma2(acc2[i2][j], a[1], b1);   // k+1
                fma2(acc2[i2][j], a[2], b2);   // k+2
                fma2(acc2[i2][j], a[3], b3);   // k+3
            }
        }
    }

    const float sc = sqrtf(128.0f);
    float* out = g_att + ((size_t)b * NSEQ + n0) * NSEQ + m0;
#pragma unroll
    for (int i2 = 0; i2 < 4; i2++)
#pragma unroll
        for (int j = 0; j < 8; j++) {
            float lo, hi;
            unpack2(acc2[i2][j], lo, hi);
            out[(size_t)(ty + 16 * i2)      * NSEQ + tx + 16 * j] = __fdiv_rn(lo, sc);
            out[(size_t)(ty + 16 * i2 + 64) * NSEQ + tx + 16 * j] = __fdiv_rn(hi, sc);
        }
}

// ---------------- K3: softmax rows in place (logits -> attention, f32) ----------------
// 64 rows per CTA -> 256 CTAs -> 2 CTAs/SM for latency hiding. Same arithmetic.
__global__ __launch_bounds__(256) void softmax_kernel() {
    __shared__ float rowbuf[NSEQ];   // 32KB
    __shared__ float  redf[8];
    __shared__ double redd[8];
    __shared__ float  s_rmax, s_S;

    const int b   = blockIdx.y;
    const int r0  = blockIdx.x * 64;
    const int tid = threadIdx.x;
    const int lane = tid & 31, wid = tid >> 5;

    for (int rr = 0; rr < 64; rr++) {
        const int row = r0 + rr;
        float* L = g_att + ((size_t)b * NSEQ + row) * NSEQ;

        float lmax = -3.0e38f;
        for (int e4 = tid; e4 < NSEQ / 4; e4 += 256) {
            float4 v = *reinterpret_cast<const float4*>(L + e4 * 4);
            *reinterpret_cast<float4*>(&rowbuf[e4 * 4]) = v;
            lmax = fmaxf(lmax, fmaxf(fmaxf(v.x, v.y), fmaxf(v.z, v.w)));
        }
#pragma unroll
        for (int o = 16; o; o >>= 1) lmax = fmaxf(lmax, __shfl_xor_sync(0xffffffffu, lmax, o));
        if (lane == 0) redf[wid] = lmax;
        __syncthreads();
        if (tid == 0) {
            float m = redf[0];
#pragma unroll
            for (int w = 1; w < 8; w++) m = fmaxf(m, redf[w]);
            s_rmax = m;
        }
        __syncthreads();
        const float rm = s_rmax;

        // exp (libdevice expf == XLA's f32 exp lowering) + fp64 row sum
        double lsum = 0.0;
        for (int e4 = tid; e4 < NSEQ / 4; e4 += 256) {
            float4 v = *reinterpret_cast<float4*>(&rowbuf[e4 * 4]);
            v.x = expf(v.x - rm); v.y = expf(v.y - rm);
            v.z = expf(v.z - rm); v.w = expf(v.w - rm);
            *reinterpret_cast<float4*>(&rowbuf[e4 * 4]) = v;
            lsum += (double)v.x + (double)v.y + (double)v.z + (double)v.w;
        }
#pragma unroll
        for (int o = 16; o; o >>= 1) lsum += __shfl_xor_sync(0xffffffffu, lsum, o);
        if (lane == 0) redd[wid] = lsum;
        __syncthreads();
        if (tid == 0) {
            double s = redd[0];
#pragma unroll
            for (int w = 1; w < 8; w++) s += redd[w];
            s_S = (float)s;
        }
        __syncthreads();
        const float Sf = s_S;

        for (int e4 = tid; e4 < NSEQ / 4; e4 += 256) {
            float4 p = *reinterpret_cast<float4*>(&rowbuf[e4 * 4]);
            p.x = __fdiv_rn(p.x, Sf); p.y = __fdiv_rn(p.y, Sf);
            p.z = __fdiv_rn(p.z, Sf); p.w = __fdiv_rn(p.w, Sf);
            *reinterpret_cast<float4*>(L + e4 * 4) = p;
        }
        __syncthreads();
    }
}

// ---------------- K3b: XLA-GPU two-stage column reduction replica (DO NOT TOUCH) ----------------
__global__ __launch_bounds__(1024) void colsum_kernel() {
    __shared__ float part[32][33];
    const int b  = blockIdx.y;
    const int m  = blockIdx.x * 32 + threadIdx.x;
    const int ty = threadIdx.y;
    const float* A = g_att + (size_t)b * NSEQ * NSEQ + m;

    float s[8];
#pragma unroll
    for (int p = 0; p < 8; p++) {
        float acc = 0.f;
#pragma unroll
        for (int k = 0; k < 32; k++)
            acc += A[(size_t)(p * 1024 + ty + 32 * k) * NSEQ];
        s[p] = acc;
    }

    float s1[8];
#pragma unroll
    for (int p = 0; p < 8; p++) {
        __syncthreads();
        part[ty][threadIdx.x] = s[p];
        __syncthreads();
        float q = part[threadIdx.x][ty];
#pragma unroll
        for (int off = 16; off; off >>= 1)
            q += __shfl_down_sync(0xffffffffu, q, off);
        s1[p] = q;
    }

    if (threadIdx.x == 0) {
        float r = ((s1[0] + s1[4]) + (s1[2] + s1[6]))
                + ((s1[1] + s1[5]) + (s1[3] + s1[7]));
        g_sel[b * NSEQ + blockIdx.x * 32 + ty] = r;
    }
}

// ---------------- K4: top-k (bitonic sort, desc value / asc index tie-break) ----------------
#define K4_SMEM (NSEQ * 8)
__global__ __launch_bounds__(1024) void topk_kernel() {
    extern __shared__ unsigned long long keys[];
    const int b = blockIdx.x;
    const int tid = threadIdx.x;

    for (int e = tid; e < NSEQ; e += 1024) {
        unsigned int u = __float_as_uint(g_sel[b * NSEQ + e]);
        u = (u & 0x80000000u) ? ~u : (u | 0x80000000u);
        u = ~u;
        keys[e] = ((unsigned long long)u << 32) | (unsigned int)e;
    }
    __syncthreads();

    for (int size = 2; size <= NSEQ; size <<= 1) {
        for (int stride = size >> 1; stride > 0; stride >>= 1) {
            for (int i = tid; i < NSEQ; i += 1024) {
                int j = i ^ stride;
                if (j > i) {
                    bool up = ((i & size) == 0);
                    unsigned long long a = keys[i], c = keys[j];
                    if ((a > c) == up) { keys[i] = c; keys[j] = a; }
                }
            }
            __syncthreads();
        }
    }

    for (int e = tid; e < MSEL; e += 1024)
        g_idx[b * MSEL + e] = (int)(keys[e] & 0xffffffffu);
}

// ---------------- K5: gather attention rows + scores @ v^T (packed FFMA2) ----------------
// V tile as row-pairs (r, r+32); P row-major with dup operand.
#define VS_STRIDE 68   // floats per packed V row (2*32 + 4)
__global__ __launch_bounds__(256) void out_kernel(float* __restrict__ out) {
    __shared__ float Vs[32 * VS_STRIDE];
    __shared__ float Ps[64][36];
    __shared__ int   srow[64];

    const int b  = blockIdx.z;
    const int c0 = blockIdx.y * 64;
    const int j0 = blockIdx.x * 64;
    const int tid = threadIdx.x;
    const int tx = tid & 15, ty = tid >> 4;

    if (tid < 64) srow[tid] = g_idx[b * MSEL + j0 + tid];
    __syncthreads();

    unsigned long long acc2[2][4];
#pragma unroll
    for (int i = 0; i < 2; i++)
#pragma unroll
        for (int j = 0; j < 4; j++) acc2[i][j] = 0ull;

    const float* vb = g_v + ((size_t)b * CCH + c0) * NSEQ;
    const float* Ab = g_att + (size_t)b * NSEQ * NSEQ;

    for (int k0 = 0; k0 < NSEQ; k0 += 32) {
#pragma unroll
        for (int e4 = tid; e4 < 512; e4 += 256) {
            int r = e4 >> 3, k4 = e4 & 7;
            float4 v = *reinterpret_cast<const float4*>(vb + (size_t)r * NSEQ + k0 + k4 * 4);
            float* vp = Vs + (r & 31) * VS_STRIDE + (r >> 5);
            vp[(k4 * 4 + 0) * 2] = v.x; vp[(k4 * 4 + 1) * 2] = v.y;
            vp[(k4 * 4 + 2) * 2] = v.z; vp[(k4 * 4 + 3) * 2] = v.w;
            float4 l = *reinterpret_cast<const float4*>(Ab + (size_t)srow[r] * NSEQ + k0 + k4 * 4);
            *reinterpret_cast<float4*>(&Ps[r][k4 * 4]) = l;
        }
        __syncthreads();
#pragma unroll
        for (int k = 0; k < 32; k += 4) {
            float4 av[2][2];
#pragma unroll
            for (int i2 = 0; i2 < 2; i2++) {
                const float4* vp = reinterpret_cast<const float4*>(Vs + (ty + 16 * i2) * VS_STRIDE + 2 * k);
                av[i2][0] = vp[0];
                av[i2][1] = vp[1];
            }
#pragma unroll
            for (int j = 0; j < 4; j++) {
                float4 pv = *reinterpret_cast<float4*>(&Ps[tx + 16 * j][k]);
                unsigned long long p0 = pack2(pv.x, pv.x);
                unsigned long long p1 = pack2(pv.y, pv.y);
                unsigned long long p2 = pack2(pv.z, pv.z);
                unsigned long long p3 = pack2(pv.w, pv.w);
#pragma unroll
                for (int i2 = 0; i2 < 2; i2++) {
                    const unsigned long long* a = reinterpret_cast<const unsigned long long*>(&av[i2][0]);
                    fma2(acc2[i2][j], a[0], p0);
                    fma2(acc2[i2][j], a[1], p1);
                    fma2(acc2[i2][j], a[2], p2);
                    fma2(acc2[i2][j], a[3], p3);
                }
            }
        }
        __syncthreads();
    }

#pragma unroll
    for (int i2 = 0; i2 < 2; i2++)
#pragma unroll
        for (int j = 0; j < 4; j++) {
            float lo, hi;
            unpack2(acc2[i2][j], lo, hi);
            out[((size_t)b * CCH + c0 + ty + 16 * i2)      * MSEL + j0 + tx + 16 * j] = lo;
            out[((size_t)b * CCH + c0 + ty + 16 * i2 + 32) * MSEL + j0 + tx + 16 * j] = hi;
        }
}

// ---------------- launch ----------------
extern "C" void kernel_launch(void* const* d_in, const int* in_sizes, int n_in,
                              void* d_out, int out_size) {
    const float* x  = (const float*)d_in[0];
    const float* Wq = (const float*)d_in[1];
    const float* Wk = (const float*)d_in[2];
    const float* Wv = (const float*)d_in[3];
    float* out = (float*)d_out;

    cudaFuncSetAttribute(energy_kernel, cudaFuncAttributeMaxDynamicSharedMemorySize, K2_SMEM);
    cudaFuncSetAttribute(topk_kernel,   cudaFuncAttributeMaxDynamicSharedMemorySize, K4_SMEM);

    qkv_kernel<<<dim3(NSEQ / 64, BATCH), 256>>>(x, Wq, Wk, Wv);
    energy_kernel<<<dim3(NSEQ / 128, NSEQ / 128, BATCH), 256, K2_SMEM>>>();
    softmax_kernel<<<dim3(128, BATCH), 256>>>();
    colsum_kernel<<<dim3(NSEQ / 32, BATCH), dim3(32, 32)>>>();
    topk_kernel<<<BATCH, 1024, K4_SMEM>>>();
    out_kernel<<<dim3(MSEL / 64, CCH / 64, BATCH), 256>>>(out);
}

// round 7
// speedup vs baseline: 1.2937x; 1.2169x over previous
#include <cuda_runtime.h>
#include <cstdint>

#define BATCH 2
#define CCH   128
#define NSEQ  8192
#define MSEL  2048

// ---------------- f32x2 packed helpers (sm_103a FFMA2 — PTX only) ----------------
__device__ __forceinline__ unsigned long long pack2(float lo, float hi) {
    unsigned long long r;
    asm("mov.b64 %0, {%1,%2};" : "=l"(r) : "f"(lo), "f"(hi));
    return r;
}
__device__ __forceinline__ void unpack2(unsigned long long v, float& lo, float& hi) {
    asm("mov.b64 {%0,%1}, %2;" : "=f"(lo), "=f"(hi) : "l"(v));
}
__device__ __forceinline__ void fma2(unsigned long long& d, unsigned long long a, unsigned long long b) {
    asm("fma.rn.f32x2 %0, %1, %2, %0;" : "+l"(d) : "l"(a), "l"(b));
}

// ---------------- scratch (static device globals; no allocation) ----------------
__device__ float g_qT[(size_t)BATCH * NSEQ * CCH];       // [b][n][c]
__device__ float g_kT[(size_t)BATCH * NSEQ * CCH];       // [b][m][c]
__device__ float g_v [(size_t)BATCH * CCH * NSEQ];       // [b][c][n]
__device__ float g_att[(size_t)BATCH * NSEQ * NSEQ];     // logits, then attention [b][n][m]
__device__ float g_sel[BATCH * NSEQ];                    // selection (XLA-order col sums)
__device__ int   g_idx[BATCH * MSEL];
__device__ float g_opart[(size_t)BATCH * 4 * CCH * MSEL];// K-split partials for output

// ---------------- dummy (shifts ncu -s 5 capture slot onto energy_kernel) ----------------
__global__ void dummy_kernel() {}

// ---------------- K1: q,k,v projections (ascending-c fma chains) ----------------
__global__ __launch_bounds__(256) void qkv_kernel(const float* __restrict__ x,
                                                  const float* __restrict__ Wq,
                                                  const float* __restrict__ Wk,
                                                  const float* __restrict__ Wv) {
    __shared__ float xs[CCH][64];
    const int b  = blockIdx.y;
    const int n0 = blockIdx.x * 64;
    const float* xb = x + (size_t)b * CCH * NSEQ;

    for (int e4 = threadIdx.x; e4 < CCH * 16; e4 += 256) {
        int ci = e4 >> 4, k4 = e4 & 15;
        float4 v = *reinterpret_cast<const float4*>(xb + (size_t)ci * NSEQ + n0 + k4 * 4);
        xs[ci][k4 * 4 + 0] = v.x; xs[ci][k4 * 4 + 1] = v.y;
        xs[ci][k4 * 4 + 2] = v.z; xs[ci][k4 * 4 + 3] = v.w;
    }
    __syncthreads();

    for (int o = threadIdx.x; o < CCH * 64; o += 256) {
        int co = o >> 6, n = o & 63;
        const float* wq = Wq + co * CCH;
        const float* wk = Wk + co * CCH;
        const float* wv = Wv + co * CCH;
        float aq = 0.f, ak = 0.f, av = 0.f;
#pragma unroll 8
        for (int ci = 0; ci < CCH; ci++) {      // strict ascending-c chain
            float xv = xs[ci][n];
            aq = fmaf(wq[ci], xv, aq);
            ak = fmaf(wk[ci], xv, ak);
            av = fmaf(wv[ci], xv, av);
        }
        g_v[((size_t)b * CCH + co) * NSEQ + n0 + n] = av;
        size_t tr = ((size_t)b * NSEQ + n0 + n) * CCH + co;
        g_qT[tr] = aq;
        g_kT[tr] = ak;
    }
}

// ---------------- K2: energy GEMM with packed FFMA2 (bit-exact chains) ----------------
#define AS_STRIDE 260
#define K2_SMEM ((64 * AS_STRIDE + 128 * 132) * 4)
__global__ __launch_bounds__(256, 1) void energy_kernel() {
    extern __shared__ float sm[];
    float* As = sm;                          // packed row-pairs [64][AS_STRIDE]
    float* Bs = sm + 64 * AS_STRIDE;         // row-major [128][132]
    const int b  = blockIdx.z;
    const int n0 = blockIdx.y * 128;
    const int m0 = blockIdx.x * 128;
    const int tid = threadIdx.x;

    const float* Ag = g_qT + ((size_t)b * NSEQ + n0) * CCH;
    const float* Bg = g_kT + ((size_t)b * NSEQ + m0) * CCH;
    for (int e4 = tid; e4 < 128 * 32; e4 += 256) {
        int r = e4 >> 5, c4 = e4 & 31;
        float4 va = *reinterpret_cast<const float4*>(Ag + r * CCH + c4 * 4);
        float4 vb = *reinterpret_cast<const float4*>(Bg + r * CCH + c4 * 4);
        float* ap = As + (r & 63) * AS_STRIDE + (r >> 6);
        ap[(c4 * 4 + 0) * 2] = va.x; ap[(c4 * 4 + 1) * 2] = va.y;
        ap[(c4 * 4 + 2) * 2] = va.z; ap[(c4 * 4 + 3) * 2] = va.w;
        *reinterpret_cast<float4*>(&Bs[r * 132 + c4 * 4]) = vb;
    }
    __syncthreads();

    const int tx = tid & 15, ty = tid >> 4;
    unsigned long long acc2[4][8];
#pragma unroll
    for (int i = 0; i < 4; i++)
#pragma unroll
        for (int j = 0; j < 8; j++) acc2[i][j] = 0ull;

#pragma unroll 2
    for (int k = 0; k < 128; k += 4) {
        float4 av[4][2];
#pragma unroll
        for (int i2 = 0; i2 < 4; i2++) {
            const float4* ap = reinterpret_cast<const float4*>(As + (ty + 16 * i2) * AS_STRIDE + 2 * k);
            av[i2][0] = ap[0];
            av[i2][1] = ap[1];
        }
#pragma unroll
        for (int j = 0; j < 8; j++) {
            float4 bv = *reinterpret_cast<const float4*>(&Bs[(tx + 16 * j) * 132 + k]);
            unsigned long long b0 = pack2(bv.x, bv.x);
            unsigned long long b1 = pack2(bv.y, bv.y);
            unsigned long long b2 = pack2(bv.z, bv.z);
            unsigned long long b3 = pack2(bv.w, bv.w);
#pragma unroll
            for (int i2 = 0; i2 < 4; i2++) {
                const unsigned long long* a = reinterpret_cast<const unsigned long long*>(&av[i2][0]);
                fma2(acc2[i2][j], a[0], b0);
                fma2(acc2[i2][j], a[1], b1);
                fma2(acc2[i2][j], a[2], b2);
                fma2(acc2[i2][j], a[3], b3);
            }
        }
    }

    const float sc = sqrtf(128.0f);
    float* out = g_att + ((size_t)b * NSEQ + n0) * NSEQ + m0;
#pragma unroll
    for (int i2 = 0; i2 < 4; i2++)
#pragma unroll
        for (int j = 0; j < 8; j++) {
            float lo, hi;
            unpack2(acc2[i2][j], lo, hi);
            out[(size_t)(ty + 16 * i2)      * NSEQ + tx + 16 * j] = __fdiv_rn(lo, sc);
            out[(size_t)(ty + 16 * i2 + 64) * NSEQ + tx + 16 * j] = __fdiv_rn(hi, sc);
        }
}

// ---------------- K3: softmax rows in place (bit-exact per row; 32 rows/CTA) ----------------
__global__ __launch_bounds__(256) void softmax_kernel() {
    __shared__ float rowbuf[NSEQ];   // 32KB
    __shared__ float  redf[8];
    __shared__ double redd[8];
    __shared__ float  s_rmax, s_S;

    const int b   = blockIdx.y;
    const int r0  = blockIdx.x * 32;
    const int tid = threadIdx.x;
    const int lane = tid & 31, wid = tid >> 5;

    for (int rr = 0; rr < 32; rr++) {
        const int row = r0 + rr;
        float* L = g_att + ((size_t)b * NSEQ + row) * NSEQ;

        float lmax = -3.0e38f;
        for (int e4 = tid; e4 < NSEQ / 4; e4 += 256) {
            float4 v = *reinterpret_cast<const float4*>(L + e4 * 4);
            *reinterpret_cast<float4*>(&rowbuf[e4 * 4]) = v;
            lmax = fmaxf(lmax, fmaxf(fmaxf(v.x, v.y), fmaxf(v.z, v.w)));
        }
#pragma unroll
        for (int o = 16; o; o >>= 1) lmax = fmaxf(lmax, __shfl_xor_sync(0xffffffffu, lmax, o));
        if (lane == 0) redf[wid] = lmax;
        __syncthreads();
        if (tid == 0) {
            float m = redf[0];
#pragma unroll
            for (int w = 1; w < 8; w++) m = fmaxf(m, redf[w]);
            s_rmax = m;
        }
        __syncthreads();
        const float rm = s_rmax;

        double lsum = 0.0;
        for (int e4 = tid; e4 < NSEQ / 4; e4 += 256) {
            float4 v = *reinterpret_cast<float4*>(&rowbuf[e4 * 4]);
            v.x = expf(v.x - rm); v.y = expf(v.y - rm);
            v.z = expf(v.z - rm); v.w = expf(v.w - rm);
            *reinterpret_cast<float4*>(&rowbuf[e4 * 4]) = v;
            lsum += (double)v.x + (double)v.y + (double)v.z + (double)v.w;
        }
#pragma unroll
        for (int o = 16; o; o >>= 1) lsum += __shfl_xor_sync(0xffffffffu, lsum, o);
        if (lane == 0) redd[wid] = lsum;
        __syncthreads();
        if (tid == 0) {
            double s = redd[0];
#pragma unroll
            for (int w = 1; w < 8; w++) s += redd[w];
            s_S = (float)s;
        }
        __syncthreads();
        const float Sf = s_S;

        for (int e4 = tid; e4 < NSEQ / 4; e4 += 256) {
            float4 p = *reinterpret_cast<float4*>(&rowbuf[e4 * 4]);
            p.x = __fdiv_rn(p.x, Sf); p.y = __fdiv_rn(p.y, Sf);
            p.z = __fdiv_rn(p.z, Sf); p.w = __fdiv_rn(p.w, Sf);
            *reinterpret_cast<float4*>(L + e4 * 4) = p;
        }
        __syncthreads();
    }
}

// ---------------- K3b: XLA-GPU two-stage column reduction replica (DO NOT TOUCH) ----------------
__global__ __launch_bounds__(1024) void colsum_kernel() {
    __shared__ float part[32][33];
    const int b  = blockIdx.y;
    const int m  = blockIdx.x * 32 + threadIdx.x;
    const int ty = threadIdx.y;
    const float* A = g_att + (size_t)b * NSEQ * NSEQ + m;

    float s[8];
#pragma unroll
    for (int p = 0; p < 8; p++) {
        float acc = 0.f;
#pragma unroll
        for (int k = 0; k < 32; k++)
            acc += A[(size_t)(p * 1024 + ty + 32 * k) * NSEQ];
        s[p] = acc;
    }

    float s1[8];
#pragma unroll
    for (int p = 0; p < 8; p++) {
        __syncthreads();
        part[ty][threadIdx.x] = s[p];
        __syncthreads();
        float q = part[threadIdx.x][ty];
#pragma unroll
        for (int off = 16; off; off >>= 1)
            q += __shfl_down_sync(0xffffffffu, q, off);
        s1[p] = q;
    }

    if (threadIdx.x == 0) {
        float r = ((s1[0] + s1[4]) + (s1[2] + s1[6]))
                + ((s1[1] + s1[5]) + (s1[3] + s1[7]));
        g_sel[b * NSEQ + blockIdx.x * 32 + ty] = r;
    }
}

// ---------------- K4: top-k (bitonic sort, desc value / asc index tie-break) ----------------
#define K4_SMEM (NSEQ * 8)
__global__ __launch_bounds__(1024) void topk_kernel() {
    extern __shared__ unsigned long long keys[];
    const int b = blockIdx.x;
    const int tid = threadIdx.x;

    for (int e = tid; e < NSEQ; e += 1024) {
        unsigned int u = __float_as_uint(g_sel[b * NSEQ + e]);
        u = (u & 0x80000000u) ? ~u : (u | 0x80000000u);
        u = ~u;
        keys[e] = ((unsigned long long)u << 32) | (unsigned int)e;
    }
    __syncthreads();

    for (int size = 2; size <= NSEQ; size <<= 1) {
        for (int stride = size >> 1; stride > 0; stride >>= 1) {
            for (int i = tid; i < NSEQ; i += 1024) {
                int j = i ^ stride;
                if (j > i) {
                    bool up = ((i & size) == 0);
                    unsigned long long a = keys[i], c = keys[j];
                    if ((a > c) == up) { keys[i] = c; keys[j] = a; }
                }
            }
            __syncthreads();
        }
    }

    for (int e = tid; e < MSEL; e += 1024)
        g_idx[b * MSEL + e] = (int)(keys[e] & 0xffffffffu);
}

// ---------------- K5: gather + scores @ v^T, K-split x4 (output tol 1e-3, reorder OK) ----------------
#define VS_STRIDE 68
__global__ __launch_bounds__(256) void out_kernel() {
    __shared__ float Vs[32 * VS_STRIDE];
    __shared__ float Ps[64][36];
    __shared__ int   srow[64];

    const int z  = blockIdx.z;           // b*4 + ksplit
    const int b  = z >> 2;
    const int ks = z & 3;
    const int c0 = blockIdx.y * 64;
    const int j0 = blockIdx.x * 64;
    const int tid = threadIdx.x;
    const int tx = tid & 15, ty = tid >> 4;

    if (tid < 64) srow[tid] = g_idx[b * MSEL + j0 + tid];
    __syncthreads();

    unsigned long long acc2[2][4];
#pragma unroll
    for (int i = 0; i < 2; i++)
#pragma unroll
        for (int j = 0; j < 4; j++) acc2[i][j] = 0ull;

    const float* vb = g_v + ((size_t)b * CCH + c0) * NSEQ;
    const float* Ab = g_att + (size_t)b * NSEQ * NSEQ;

    const int kbeg = ks * (NSEQ / 4), kend = kbeg + NSEQ / 4;
    for (int k0 = kbeg; k0 < kend; k0 += 32) {
#pragma unroll
        for (int e4 = tid; e4 < 512; e4 += 256) {
            int r = e4 >> 3, k4 = e4 & 7;
            float4 v = *reinterpret_cast<const float4*>(vb + (size_t)r * NSEQ + k0 + k4 * 4);
            float* vp = Vs + (r & 31) * VS_STRIDE + (r >> 5);
            vp[(k4 * 4 + 0) * 2] = v.x; vp[(k4 * 4 + 1) * 2] = v.y;
            vp[(k4 * 4 + 2) * 2] = v.z; vp[(k4 * 4 + 3) * 2] = v.w;
            float4 l = *reinterpret_cast<const float4*>(Ab + (size_t)srow[r] * NSEQ + k0 + k4 * 4);
            *reinterpret_cast<float4*>(&Ps[r][k4 * 4]) = l;
        }
        __syncthreads();
#pragma unroll
        for (int k = 0; k < 32; k += 4) {
            float4 av[2][2];
#pragma unroll
            for (int i2 = 0; i2 < 2; i2++) {
                const float4* vp = reinterpret_cast<const float4*>(Vs + (ty + 16 * i2) * VS_STRIDE + 2 * k);
                av[i2][0] = vp[0];
                av[i2][1] = vp[1];
            }
#pragma unroll
            for (int j = 0; j < 4; j++) {
                float4 pv = *reinterpret_cast<float4*>(&Ps[tx + 16 * j][k]);
                unsigned long long p0 = pack2(pv.x, pv.x);
                unsigned long long p1 = pack2(pv.y, pv.y);
                unsigned long long p2 = pack2(pv.z, pv.z);
                unsigned long long p3 = pack2(pv.w, pv.w);
#pragma unroll
                for (int i2 = 0; i2 < 2; i2++) {
                    const unsigned long long* a = reinterpret_cast<const unsigned long long*>(&av[i2][0]);
                    fma2(acc2[i2][j], a[0], p0);
                    fma2(acc2[i2][j], a[1], p1);
                    fma2(acc2[i2][j], a[2], p2);
                    fma2(acc2[i2][j], a[3], p3);
                }
            }
        }
        __syncthreads();
    }

    float* op = g_opart + (size_t)z * CCH * MSEL;
#pragma unroll
    for (int i2 = 0; i2 < 2; i2++)
#pragma unroll
        for (int j = 0; j < 4; j++) {
            float lo, hi;
            unpack2(acc2[i2][j], lo, hi);
            op[(size_t)(c0 + ty + 16 * i2)      * MSEL + j0 + tx + 16 * j] = lo;
            op[(size_t)(c0 + ty + 16 * i2 + 32) * MSEL + j0 + tx + 16 * j] = hi;
        }
}

// ---------------- K5b: combine K-split partials ----------------
__global__ __launch_bounds__(256) void combine_kernel(float* __restrict__ out) {
    const int b = blockIdx.y;
    const size_t e4 = (size_t)blockIdx.x * 256 + threadIdx.x;   // float4 index within [C*M/4]
    const float* p0 = g_opart + (size_t)(b * 4 + 0) * CCH * MSEL;
    const float* p1 = g_opart + (size_t)(b * 4 + 1) * CCH * MSEL;
    const float* p2 = g_opart + (size_t)(b * 4 + 2) * CCH * MSEL;
    const float* p3 = g_opart + (size_t)(b * 4 + 3) * CCH * MSEL;
    float4 a = reinterpret_cast<const float4*>(p0)[e4];
    float4 c = reinterpret_cast<const float4*>(p1)[e4];
    float4 d = reinterpret_cast<const float4*>(p2)[e4];
    float4 f = reinterpret_cast<const float4*>(p3)[e4];
    float4 r;
    r.x = ((a.x + c.x) + d.x) + f.x;
    r.y = ((a.y + c.y) + d.y) + f.y;
    r.z = ((a.z + c.z) + d.z) + f.z;
    r.w = ((a.w + c.w) + d.w) + f.w;
    reinterpret_cast<float4*>(out + (size_t)b * CCH * MSEL)[e4] = r;
}

// ---------------- launch ----------------
extern "C" void kernel_launch(void* const* d_in, const int* in_sizes, int n_in,
                              void* d_out, int out_size) {
    const float* x  = (const float*)d_in[0];
    const float* Wq = (const float*)d_in[1];
    const float* Wk = (const float*)d_in[2];
    const float* Wv = (const float*)d_in[3];
    float* out = (float*)d_out;

    cudaFuncSetAttribute(energy_kernel, cudaFuncAttributeMaxDynamicSharedMemorySize, K2_SMEM);
    cudaFuncSetAttribute(topk_kernel,   cudaFuncAttributeMaxDynamicSharedMemorySize, K4_SMEM);

    qkv_kernel<<<dim3(NSEQ / 64, BATCH), 256>>>(x, Wq, Wk, Wv);
    dummy_kernel<<<1, 32>>>();   // shift ncu -s 5 slot ...
    dummy_kernel<<<1, 32>>>();   // ... so energy_kernel is global launch #6
    energy_kernel<<<dim3(NSEQ / 128, NSEQ / 128, BATCH), 256, K2_SMEM>>>();
    softmax_kernel<<<dim3(256, BATCH), 256>>>();
    colsum_kernel<<<dim3(NSEQ / 32, BATCH), dim3(32, 32)>>>();
    topk_kernel<<<BATCH, 1024, K4_SMEM>>>();
    out_kernel<<<dim3(MSEL / 64, CCH / 64, BATCH * 4), 256>>>();
    combine_kernel<<<dim3(CCH * MSEL / 4 / 256, BATCH), 256>>>(out);
}

// round 8
// speedup vs baseline: 1.3383x; 1.0345x over previous
#include <cuda_runtime.h>
#include <cstdint>

#define BATCH 2
#define CCH   128
#define NSEQ  8192
#define MSEL  2048

// ---------------- f32x2 packed helpers (sm_103a FFMA2 — PTX only) ----------------
__device__ __forceinline__ unsigned long long pack2(float lo, float hi) {
    unsigned long long r;
    asm("mov.b64 %0, {%1,%2};" : "=l"(r) : "f"(lo), "f"(hi));
    return r;
}
__device__ __forceinline__ void unpack2(unsigned long long v, float& lo, float& hi) {
    asm("mov.b64 {%0,%1}, %2;" : "=f"(lo), "=f"(hi) : "l"(v));
}
__device__ __forceinline__ void fma2(unsigned long long& d, unsigned long long a, unsigned long long b) {
    asm("fma.rn.f32x2 %0, %1, %2, %0;" : "+l"(d) : "l"(a), "l"(b));
}

// ---------------- scratch (static device globals; no allocation) ----------------
__device__ float g_qT[(size_t)BATCH * NSEQ * CCH];       // [b][n][c]
__device__ float g_kT[(size_t)BATCH * NSEQ * CCH];       // [b][m][c]
__device__ float g_v [(size_t)BATCH * CCH * NSEQ];       // [b][c][n]
__device__ float g_att[(size_t)BATCH * NSEQ * NSEQ];     // logits, then attention [b][n][m]
__device__ float g_sel[BATCH * NSEQ];                    // selection (XLA-order col sums)
__device__ int   g_idx[BATCH * MSEL];
__device__ float g_opart[(size_t)BATCH * 4 * CCH * MSEL];// K-split partials for output

// ---------------- dummy (keeps ncu capture slot on energy_kernel) ----------------
__global__ void dummy_kernel() {}

// ---------------- K1: q,k,v projections (ascending-c fma chains) ----------------
__global__ __launch_bounds__(256) void qkv_kernel(const float* __restrict__ x,
                                                  const float* __restrict__ Wq,
                                                  const float* __restrict__ Wk,
                                                  const float* __restrict__ Wv) {
    __shared__ float xs[CCH][64];
    const int b  = blockIdx.y;
    const int n0 = blockIdx.x * 64;
    const float* xb = x + (size_t)b * CCH * NSEQ;

    for (int e4 = threadIdx.x; e4 < CCH * 16; e4 += 256) {
        int ci = e4 >> 4, k4 = e4 & 15;
        float4 v = *reinterpret_cast<const float4*>(xb + (size_t)ci * NSEQ + n0 + k4 * 4);
        xs[ci][k4 * 4 + 0] = v.x; xs[ci][k4 * 4 + 1] = v.y;
        xs[ci][k4 * 4 + 2] = v.z; xs[ci][k4 * 4 + 3] = v.w;
    }
    __syncthreads();

    for (int o = threadIdx.x; o < CCH * 64; o += 256) {
        int co = o >> 6, n = o & 63;
        const float* wq = Wq + co * CCH;
        const float* wk = Wk + co * CCH;
        const float* wv = Wv + co * CCH;
        float aq = 0.f, ak = 0.f, av = 0.f;
#pragma unroll 8
        for (int ci = 0; ci < CCH; ci++) {      // strict ascending-c chain
            float xv = xs[ci][n];
            aq = fmaf(wq[ci], xv, aq);
            ak = fmaf(wk[ci], xv, ak);
            av = fmaf(wv[ci], xv, av);
        }
        g_v[((size_t)b * CCH + co) * NSEQ + n0 + n] = av;
        size_t tr = ((size_t)b * NSEQ + n0 + n) * CCH + co;
        g_qT[tr] = aq;
        g_kT[tr] = ak;
    }
}

// ---------------- K2: energy GEMM, packed FFMA2, 512 threads (16 warps/SM) ----------------
// Same 128x128 tile; thread (tx 0..15, tyy 0..31) owns packed row-pairs
// (tyy+32*i2, +64) x columns (tx+16*j). Ascending-k chain per output -> bit-exact.
#define AS_STRIDE 260
#define K2_SMEM ((64 * AS_STRIDE + 128 * 132) * 4)
__global__ __launch_bounds__(512, 1) void energy_kernel() {
    extern __shared__ float sm[];
    float* As = sm;                          // packed row-pairs [64][AS_STRIDE]
    float* Bs = sm + 64 * AS_STRIDE;         // row-major [128][132]
    const int b  = blockIdx.z;
    const int n0 = blockIdx.y * 128;
    const int m0 = blockIdx.x * 128;
    const int tid = threadIdx.x;

    const float* Ag = g_qT + ((size_t)b * NSEQ + n0) * CCH;
    const float* Bg = g_kT + ((size_t)b * NSEQ + m0) * CCH;
    for (int e4 = tid; e4 < 128 * 32; e4 += 512) {
        int r = e4 >> 5, c4 = e4 & 31;
        float4 va = *reinterpret_cast<const float4*>(Ag + r * CCH + c4 * 4);
        float4 vb = *reinterpret_cast<const float4*>(Bg + r * CCH + c4 * 4);
        float* ap = As + (r & 63) * AS_STRIDE + (r >> 6);
        ap[(c4 * 4 + 0) * 2] = va.x; ap[(c4 * 4 + 1) * 2] = va.y;
        ap[(c4 * 4 + 2) * 2] = va.z; ap[(c4 * 4 + 3) * 2] = va.w;
        *reinterpret_cast<float4*>(&Bs[r * 132 + c4 * 4]) = vb;
    }
    __syncthreads();

    const int tx = tid & 15, tyy = tid >> 4;   // 16 x 32
    unsigned long long acc2[2][8];
#pragma unroll
    for (int i = 0; i < 2; i++)
#pragma unroll
        for (int j = 0; j < 8; j++) acc2[i][j] = 0ull;

#pragma unroll 2
    for (int k = 0; k < 128; k += 4) {
        float4 av[2][2];
#pragma unroll
        for (int i2 = 0; i2 < 2; i2++) {
            const float4* ap = reinterpret_cast<const float4*>(As + (tyy + 32 * i2) * AS_STRIDE + 2 * k);
            av[i2][0] = ap[0];
            av[i2][1] = ap[1];
        }
#pragma unroll
        for (int j = 0; j < 8; j++) {
            float4 bv = *reinterpret_cast<const float4*>(&Bs[(tx + 16 * j) * 132 + k]);
            unsigned long long b0 = pack2(bv.x, bv.x);
            unsigned long long b1 = pack2(bv.y, bv.y);
            unsigned long long b2 = pack2(bv.z, bv.z);
            unsigned long long b3 = pack2(bv.w, bv.w);
#pragma unroll
            for (int i2 = 0; i2 < 2; i2++) {
                const unsigned long long* a = reinterpret_cast<const unsigned long long*>(&av[i2][0]);
                fma2(acc2[i2][j], a[0], b0);
                fma2(acc2[i2][j], a[1], b1);
                fma2(acc2[i2][j], a[2], b2);
                fma2(acc2[i2][j], a[3], b3);
            }
        }
    }

    const float sc = sqrtf(128.0f);
    float* out = g_att + ((size_t)b * NSEQ + n0) * NSEQ + m0;
#pragma unroll
    for (int i2 = 0; i2 < 2; i2++)
#pragma unroll
        for (int j = 0; j < 8; j++) {
            float lo, hi;
            unpack2(acc2[i2][j], lo, hi);
            out[(size_t)(tyy + 32 * i2)      * NSEQ + tx + 16 * j] = __fdiv_rn(lo, sc);
            out[(size_t)(tyy + 32 * i2 + 64) * NSEQ + tx + 16 * j] = __fdiv_rn(hi, sc);
        }
}

// ---------------- K3: softmax rows in place (bit-exact per row; 32 rows/CTA) ----------------
__global__ __launch_bounds__(256) void softmax_kernel() {
    __shared__ float rowbuf[NSEQ];   // 32KB
    __shared__ float  redf[8];
    __shared__ double redd[8];
    __shared__ float  s_rmax, s_S;

    const int b   = blockIdx.y;
    const int r0  = blockIdx.x * 32;
    const int tid = threadIdx.x;
    const int lane = tid & 31, wid = tid >> 5;

    for (int rr = 0; rr < 32; rr++) {
        const int row = r0 + rr;
        float* L = g_att + ((size_t)b * NSEQ + row) * NSEQ;

        float lmax = -3.0e38f;
        for (int e4 = tid; e4 < NSEQ / 4; e4 += 256) {
            float4 v = *reinterpret_cast<const float4*>(L + e4 * 4);
            *reinterpret_cast<float4*>(&rowbuf[e4 * 4]) = v;
            lmax = fmaxf(lmax, fmaxf(fmaxf(v.x, v.y), fmaxf(v.z, v.w)));
        }
#pragma unroll
        for (int o = 16; o; o >>= 1) lmax = fmaxf(lmax, __shfl_xor_sync(0xffffffffu, lmax, o));
        if (lane == 0) redf[wid] = lmax;
        __syncthreads();
        if (tid == 0) {
            float m = redf[0];
#pragma unroll
            for (int w = 1; w < 8; w++) m = fmaxf(m, redf[w]);
            s_rmax = m;
        }
        __syncthreads();
        const float rm = s_rmax;

        double lsum = 0.0;
        for (int e4 = tid; e4 < NSEQ / 4; e4 += 256) {
            float4 v = *reinterpret_cast<float4*>(&rowbuf[e4 * 4]);
            v.x = expf(v.x - rm); v.y = expf(v.y - rm);
            v.z = expf(v.z - rm); v.w = expf(v.w - rm);
            *reinterpret_cast<float4*>(&rowbuf[e4 * 4]) = v;
            lsum += (double)v.x + (double)v.y + (double)v.z + (double)v.w;
        }
#pragma unroll
        for (int o = 16; o; o >>= 1) lsum += __shfl_xor_sync(0xffffffffu, lsum, o);
        if (lane == 0) redd[wid] = lsum;
        __syncthreads();
        if (tid == 0) {
            double s = redd[0];
#pragma unroll
            for (int w = 1; w < 8; w++) s += redd[w];
            s_S = (float)s;
        }
        __syncthreads();
        const float Sf = s_S;

        for (int e4 = tid; e4 < NSEQ / 4; e4 += 256) {
            float4 p = *reinterpret_cast<float4*>(&rowbuf[e4 * 4]);
            p.x = __fdiv_rn(p.x, Sf); p.y = __fdiv_rn(p.y, Sf);
            p.z = __fdiv_rn(p.z, Sf); p.w = __fdiv_rn(p.w, Sf);
            *reinterpret_cast<float4*>(L + e4 * 4) = p;
        }
        __syncthreads();
    }
}

// ---------------- K3b: XLA-GPU two-stage column reduction replica (DO NOT TOUCH) ----------------
__global__ __launch_bounds__(1024) void colsum_kernel() {
    __shared__ float part[32][33];
    const int b  = blockIdx.y;
    const int m  = blockIdx.x * 32 + threadIdx.x;
    const int ty = threadIdx.y;
    const float* A = g_att + (size_t)b * NSEQ * NSEQ + m;

    float s[8];
#pragma unroll
    for (int p = 0; p < 8; p++) {
        float acc = 0.f;
#pragma unroll
        for (int k = 0; k < 32; k++)
            acc += A[(size_t)(p * 1024 + ty + 32 * k) * NSEQ];
        s[p] = acc;
    }

    float s1[8];
#pragma unroll
    for (int p = 0; p < 8; p++) {
        __syncthreads();
        part[ty][threadIdx.x] = s[p];
        __syncthreads();
        float q = part[threadIdx.x][ty];
#pragma unroll
        for (int off = 16; off; off >>= 1)
            q += __shfl_down_sync(0xffffffffu, q, off);
        s1[p] = q;
    }

    if (threadIdx.x == 0) {
        float r = ((s1[0] + s1[4]) + (s1[2] + s1[6]))
                + ((s1[1] + s1[5]) + (s1[3] + s1[7]));
        g_sel[b * NSEQ + blockIdx.x * 32 + ty] = r;
    }
}

// ---------------- K4: top-k (bitonic sort, desc value / asc index tie-break) ----------------
#define K4_SMEM (NSEQ * 8)
__global__ __launch_bounds__(1024) void topk_kernel() {
    extern __shared__ unsigned long long keys[];
    const int b = blockIdx.x;
    const int tid = threadIdx.x;

    for (int e = tid; e < NSEQ; e += 1024) {
        unsigned int u = __float_as_uint(g_sel[b * NSEQ + e]);
        u = (u & 0x80000000u) ? ~u : (u | 0x80000000u);
        u = ~u;
        keys[e] = ((unsigned long long)u << 32) | (unsigned int)e;
    }
    __syncthreads();

    for (int size = 2; size <= NSEQ; size <<= 1) {
        for (int stride = size >> 1; stride > 0; stride >>= 1) {
            for (int i = tid; i < NSEQ; i += 1024) {
                int j = i ^ stride;
                if (j > i) {
                    bool up = ((i & size) == 0);
                    unsigned long long a = keys[i], c = keys[j];
                    if ((a > c) == up) { keys[i] = c; keys[j] = a; }
                }
            }
            __syncthreads();
        }
    }

    for (int e = tid; e < MSEL; e += 1024)
        g_idx[b * MSEL + e] = (int)(keys[e] & 0xffffffffu);
}

// ---------------- K5: gather + scores @ v^T, K-split x4 ----------------
#define VS_STRIDE 68
__global__ __launch_bounds__(256) void out_kernel() {
    __shared__ float Vs[32 * VS_STRIDE];
    __shared__ float Ps[64][36];
    __shared__ int   srow[64];

    const int z  = blockIdx.z;           // b*4 + ksplit
    const int b  = z >> 2;
    const int ks = z & 3;
    const int c0 = blockIdx.y * 64;
    const int j0 = blockIdx.x * 64;
    const int tid = threadIdx.x;
    const int tx = tid & 15, ty = tid >> 4;

    if (tid < 64) srow[tid] = g_idx[b * MSEL + j0 + tid];
    __syncthreads();

    unsigned long long acc2[2][4];
#pragma unroll
    for (int i = 0; i < 2; i++)
#pragma unroll
        for (int j = 0; j < 4; j++) acc2[i][j] = 0ull;

    const float* vb = g_v + ((size_t)b * CCH + c0) * NSEQ;
    const float* Ab = g_att + (size_t)b * NSEQ * NSEQ;

    const int kbeg = ks * (NSEQ / 4), kend = kbeg + NSEQ / 4;
    for (int k0 = kbeg; k0 < kend; k0 += 32) {
#pragma unroll
        for (int e4 = tid; e4 < 512; e4 += 256) {
            int r = e4 >> 3, k4 = e4 & 7;
            float4 v = *reinterpret_cast<const float4*>(vb + (size_t)r * NSEQ + k0 + k4 * 4);
            float* vp = Vs + (r & 31) * VS_STRIDE + (r >> 5);
            vp[(k4 * 4 + 0) * 2] = v.x; vp[(k4 * 4 + 1) * 2] = v.y;
            vp[(k4 * 4 + 2) * 2] = v.z; vp[(k4 * 4 + 3) * 2] = v.w;
            float4 l = *reinterpret_cast<const float4*>(Ab + (size_t)srow[r] * NSEQ + k0 + k4 * 4);
            *reinterpret_cast<float4*>(&Ps[r][k4 * 4]) = l;
        }
        __syncthreads();
#pragma unroll
        for (int k = 0; k < 32; k += 4) {
            float4 av[2][2];
#pragma unroll
            for (int i2 = 0; i2 < 2; i2++) {
                const float4* vp = reinterpret_cast<const float4*>(Vs + (ty + 16 * i2) * VS_STRIDE + 2 * k);
                av[i2][0] = vp[0];
                av[i2][1] = vp[1];
            }
#pragma unroll
            for (int j = 0; j < 4; j++) {
                float4 pv = *reinterpret_cast<float4*>(&Ps[tx + 16 * j][k]);
                unsigned long long p0 = pack2(pv.x, pv.x);
                unsigned long long p1 = pack2(pv.y, pv.y);
                unsigned long long p2 = pack2(pv.z, pv.z);
                unsigned long long p3 = pack2(pv.w, pv.w);
#pragma unroll
                for (int i2 = 0; i2 < 2; i2++) {
                    const unsigned long long* a = reinterpret_cast<const unsigned long long*>(&av[i2][0]);
                    fma2(acc2[i2][j], a[0], p0);
                    fma2(acc2[i2][j], a[1], p1);
                    fma2(acc2[i2][j], a[2], p2);
                    fma2(acc2[i2][j], a[3], p3);
                }
            }
        }
        __syncthreads();
    }

    float* op = g_opart + (size_t)z * CCH * MSEL;
#pragma unroll
    for (int i2 = 0; i2 < 2; i2++)
#pragma unroll
        for (int j = 0; j < 4; j++) {
            float lo, hi;
            unpack2(acc2[i2][j], lo, hi);
            op[(size_t)(c0 + ty + 16 * i2)      * MSEL + j0 + tx + 16 * j] = lo;
            op[(size_t)(c0 + ty + 16 * i2 + 32) * MSEL + j0 + tx + 16 * j] = hi;
        }
}

// ---------------- K5b: combine K-split partials ----------------
__global__ __launch_bounds__(256) void combine_kernel(float* __restrict__ out) {
    const int b = blockIdx.y;
    const size_t e4 = (size_t)blockIdx.x * 256 + threadIdx.x;
    const float* p0 = g_opart + (size_t)(b * 4 + 0) * CCH * MSEL;
    const float* p1 = g_opart + (size_t)(b * 4 + 1) * CCH * MSEL;
    const float* p2 = g_opart + (size_t)(b * 4 + 2) * CCH * MSEL;
    const float* p3 = g_opart + (size_t)(b * 4 + 3) * CCH * MSEL;
    float4 a = reinterpret_cast<const float4*>(p0)[e4];
    float4 c = reinterpret_cast<const float4*>(p1)[e4];
    float4 d = reinterpret_cast<const float4*>(p2)[e4];
    float4 f = reinterpret_cast<const float4*>(p3)[e4];
    float4 r;
    r.x = ((a.x + c.x) + d.x) + f.x;
    r.y = ((a.y + c.y) + d.y) + f.y;
    r.z = ((a.z + c.z) + d.z) + f.z;
    r.w = ((a.w + c.w) + d.w) + f.w;
    reinterpret_cast<float4*>(out + (size_t)b * CCH * MSEL)[e4] = r;
}

// ---------------- launch ----------------
extern "C" void kernel_launch(void* const* d_in, const int* in_sizes, int n_in,
                              void* d_out, int out_size) {
    const float* x  = (const float*)d_in[0];
    const float* Wq = (const float*)d_in[1];
    const float* Wk = (const float*)d_in[2];
    const float* Wv = (const float*)d_in[3];
    float* out = (float*)d_out;

    cudaFuncSetAttribute(energy_kernel, cudaFuncAttributeMaxDynamicSharedMemorySize, K2_SMEM);
    cudaFuncSetAttribute(topk_kernel,   cudaFuncAttributeMaxDynamicSharedMemorySize, K4_SMEM);

    qkv_kernel<<<dim3(NSEQ / 64, BATCH), 256>>>(x, Wq, Wk, Wv);
    dummy_kernel<<<1, 32>>>();   // keep capture slot ...
    dummy_kernel<<<1, 32>>>();   // ... on energy_kernel
    energy_kernel<<<dim3(NSEQ / 128, NSEQ / 128, BATCH), 512, K2_SMEM>>>();
    softmax_kernel<<<dim3(256, BATCH), 256>>>();
    colsum_kernel<<<dim3(NSEQ / 32, BATCH), dim3(32, 32)>>>();
    topk_kernel<<<BATCH, 1024, K4_SMEM>>>();
    out_kernel<<<dim3(MSEL / 64, CCH / 64, BATCH * 4), 256>>>();
    combine_kernel<<<dim3(CCH * MSEL / 4 / 256, BATCH), 256>>>(out);
}

// round 9
// speedup vs baseline: 1.7851x; 1.3338x over previous
#include <cuda_runtime.h>
#include <cstdint>

#define BATCH 2
#define CCH   128
#define NSEQ  8192
#define MSEL  2048

// ---------------- f32x2 packed helpers (sm_103a FFMA2 — PTX only) ----------------
__device__ __forceinline__ unsigned long long pack2(float lo, float hi) {
    unsigned long long r;
    asm("mov.b64 %0, {%1,%2};" : "=l"(r) : "f"(lo), "f"(hi));
    return r;
}
__device__ __forceinline__ void unpack2(unsigned long long v, float& lo, float& hi) {
    asm("mov.b64 {%0,%1}, %2;" : "=f"(lo), "=f"(hi) : "l"(v));
}
__device__ __forceinline__ void fma2(unsigned long long& d, unsigned long long a, unsigned long long b) {
    asm("fma.rn.f32x2 %0, %1, %2, %0;" : "+l"(d) : "l"(a), "l"(b));
}

// ---------------- scratch (static device globals; no allocation) ----------------
__device__ float g_qT[(size_t)BATCH * NSEQ * CCH];       // [b][n][c]
__device__ float g_kT[(size_t)BATCH * NSEQ * CCH];       // [b][m][c]
__device__ float g_v [(size_t)BATCH * CCH * NSEQ];       // [b][c][n]
__device__ float g_att[(size_t)BATCH * NSEQ * NSEQ];     // logits, then attention [b][n][m]
__device__ float g_sel[BATCH * NSEQ];                    // selection (XLA-order col sums)
__device__ int   g_idx[BATCH * MSEL];
__device__ float g_opart[(size_t)BATCH * 4 * CCH * MSEL];// K-split partials for output

// ---------------- dummy (moves ncu capture slot onto softmax this round) ----------------
__global__ void dummy_kernel() {}

// ---------------- K1: q,k,v projections (ascending-c fma chains) ----------------
__global__ __launch_bounds__(256) void qkv_kernel(const float* __restrict__ x,
                                                  const float* __restrict__ Wq,
                                                  const float* __restrict__ Wk,
                                                  const float* __restrict__ Wv) {
    __shared__ float xs[CCH][64];
    const int b  = blockIdx.y;
    const int n0 = blockIdx.x * 64;
    const float* xb = x + (size_t)b * CCH * NSEQ;

    for (int e4 = threadIdx.x; e4 < CCH * 16; e4 += 256) {
        int ci = e4 >> 4, k4 = e4 & 15;
        float4 v = *reinterpret_cast<const float4*>(xb + (size_t)ci * NSEQ + n0 + k4 * 4);
        xs[ci][k4 * 4 + 0] = v.x; xs[ci][k4 * 4 + 1] = v.y;
        xs[ci][k4 * 4 + 2] = v.z; xs[ci][k4 * 4 + 3] = v.w;
    }
    __syncthreads();

    for (int o = threadIdx.x; o < CCH * 64; o += 256) {
        int co = o >> 6, n = o & 63;
        const float* wq = Wq + co * CCH;
        const float* wk = Wk + co * CCH;
        const float* wv = Wv + co * CCH;
        float aq = 0.f, ak = 0.f, av = 0.f;
#pragma unroll 8
        for (int ci = 0; ci < CCH; ci++) {      // strict ascending-c chain
            float xv = xs[ci][n];
            aq = fmaf(wq[ci], xv, aq);
            ak = fmaf(wk[ci], xv, ak);
            av = fmaf(wv[ci], xv, av);
        }
        g_v[((size_t)b * CCH + co) * NSEQ + n0 + n] = av;
        size_t tr = ((size_t)b * NSEQ + n0 + n) * CCH + co;
        g_qT[tr] = aq;
        g_kT[tr] = ak;
    }
}

// ---------------- K2: energy GEMM, 256x128 tile, packed FFMA2, 512 threads ----------------
// A rows 256 stored as packed pairs (r, r+128); thread (tx 0..15, tyy 0..31) owns
// row-pairs tyy+32*i2 (i2<4) x cols tx+16*j (j<8). Ascending-k chain -> bit-exact.
#define AS_STRIDE 260
#define K2_SMEM ((128 * AS_STRIDE + 128 * 132) * 4)
__global__ __launch_bounds__(512, 1) void energy_kernel() {
    extern __shared__ float sm[];
    float* As = sm;                          // packed row-pairs [128][AS_STRIDE]
    float* Bs = sm + 128 * AS_STRIDE;        // row-major [128][132]
    const int b  = blockIdx.z;
    const int n0 = blockIdx.y * 256;
    const int m0 = blockIdx.x * 128;
    const int tid = threadIdx.x;

    const float* Ag = g_qT + ((size_t)b * NSEQ + n0) * CCH;
    const float* Bg = g_kT + ((size_t)b * NSEQ + m0) * CCH;
    for (int e4 = tid; e4 < 256 * 32; e4 += 512) {
        int r = e4 >> 5, c4 = e4 & 31;
        float4 va = *reinterpret_cast<const float4*>(Ag + r * CCH + c4 * 4);
        float* ap = As + (r & 127) * AS_STRIDE + (r >> 7);
        ap[(c4 * 4 + 0) * 2] = va.x; ap[(c4 * 4 + 1) * 2] = va.y;
        ap[(c4 * 4 + 2) * 2] = va.z; ap[(c4 * 4 + 3) * 2] = va.w;
        if (r < 128) {
            float4 vb = *reinterpret_cast<const float4*>(Bg + r * CCH + c4 * 4);
            *reinterpret_cast<float4*>(&Bs[r * 132 + c4 * 4]) = vb;
        }
    }
    __syncthreads();

    const int tx = tid & 15, tyy = tid >> 4;   // 16 x 32
    unsigned long long acc2[4][8];
#pragma unroll
    for (int i = 0; i < 4; i++)
#pragma unroll
        for (int j = 0; j < 8; j++) acc2[i][j] = 0ull;

    for (int k = 0; k < 128; k += 4) {
        float4 av[4][2];
#pragma unroll
        for (int i2 = 0; i2 < 4; i2++) {
            const float4* ap = reinterpret_cast<const float4*>(As + (tyy + 32 * i2) * AS_STRIDE + 2 * k);
            av[i2][0] = ap[0];
            av[i2][1] = ap[1];
        }
#pragma unroll
        for (int j = 0; j < 8; j++) {
            float4 bv = *reinterpret_cast<const float4*>(&Bs[(tx + 16 * j) * 132 + k]);
            unsigned long long b0 = pack2(bv.x, bv.x);
            unsigned long long b1 = pack2(bv.y, bv.y);
            unsigned long long b2 = pack2(bv.z, bv.z);
            unsigned long long b3 = pack2(bv.w, bv.w);
#pragma unroll
            for (int i2 = 0; i2 < 4; i2++) {
                const unsigned long long* a = reinterpret_cast<const unsigned long long*>(&av[i2][0]);
                fma2(acc2[i2][j], a[0], b0);
                fma2(acc2[i2][j], a[1], b1);
                fma2(acc2[i2][j], a[2], b2);
                fma2(acc2[i2][j], a[3], b3);
            }
        }
    }

    const float sc = sqrtf(128.0f);
    float* out = g_att + ((size_t)b * NSEQ + n0) * NSEQ + m0;
#pragma unroll
    for (int i2 = 0; i2 < 4; i2++)
#pragma unroll
        for (int j = 0; j < 8; j++) {
            float lo, hi;
            unpack2(acc2[i2][j], lo, hi);
            out[(size_t)(tyy + 32 * i2)       * NSEQ + tx + 16 * j] = __fdiv_rn(lo, sc);
            out[(size_t)(tyy + 32 * i2 + 128) * NSEQ + tx + 16 * j] = __fdiv_rn(hi, sc);
        }
}

// ---------------- K3: softmax rows in place; Kahan f32 row sum (fp64 only to combine) ----------------
__global__ __launch_bounds__(256) void softmax_kernel() {
    __shared__ float rowbuf[NSEQ];   // 32KB
    __shared__ float  redf[8];
    __shared__ double redd[8];
    __shared__ float  s_rmax, s_S;

    const int b   = blockIdx.y;
    const int r0  = blockIdx.x * 32;
    const int tid = threadIdx.x;
    const int lane = tid & 31, wid = tid >> 5;

    for (int rr = 0; rr < 32; rr++) {
        const int row = r0 + rr;
        float* L = g_att + ((size_t)b * NSEQ + row) * NSEQ;

        float lmax = -3.0e38f;
        for (int e4 = tid; e4 < NSEQ / 4; e4 += 256) {
            float4 v = *reinterpret_cast<const float4*>(L + e4 * 4);
            *reinterpret_cast<float4*>(&rowbuf[e4 * 4]) = v;
            lmax = fmaxf(lmax, fmaxf(fmaxf(v.x, v.y), fmaxf(v.z, v.w)));
        }
#pragma unroll
        for (int o = 16; o; o >>= 1) lmax = fmaxf(lmax, __shfl_xor_sync(0xffffffffu, lmax, o));
        if (lane == 0) redf[wid] = lmax;
        __syncthreads();
        if (tid == 0) {
            float m = redf[0];
#pragma unroll
            for (int w = 1; w < 8; w++) m = fmaxf(m, redf[w]);
            s_rmax = m;
        }
        __syncthreads();
        const float rm = s_rmax;

        // exp (libdevice expf) + Kahan f32 per-thread sum (fp32 pipe, not fp64)
        float ksum = 0.f, kc = 0.f;
        for (int e4 = tid; e4 < NSEQ / 4; e4 += 256) {
            float4 v = *reinterpret_cast<float4*>(&rowbuf[e4 * 4]);
            v.x = expf(v.x - rm); v.y = expf(v.y - rm);
            v.z = expf(v.z - rm); v.w = expf(v.w - rm);
            *reinterpret_cast<float4*>(&rowbuf[e4 * 4]) = v;
#pragma unroll
            for (int u = 0; u < 4; u++) {
                float val = (&v.x)[u];
                float y = __fsub_rn(val, kc);
                float t = __fadd_rn(ksum, y);
                kc = __fsub_rn(__fsub_rn(t, ksum), y);
                ksum = t;
            }
        }
        double lsum = (double)ksum + (double)kc;
#pragma unroll
        for (int o = 16; o; o >>= 1) lsum += __shfl_xor_sync(0xffffffffu, lsum, o);
        if (lane == 0) redd[wid] = lsum;
        __syncthreads();
        if (tid == 0) {
            double s = redd[0];
#pragma unroll
            for (int w = 1; w < 8; w++) s += redd[w];
            s_S = (float)s;
        }
        __syncthreads();
        const float Sf = s_S;

        for (int e4 = tid; e4 < NSEQ / 4; e4 += 256) {
            float4 p = *reinterpret_cast<float4*>(&rowbuf[e4 * 4]);
            p.x = __fdiv_rn(p.x, Sf); p.y = __fdiv_rn(p.y, Sf);
            p.z = __fdiv_rn(p.z, Sf); p.w = __fdiv_rn(p.w, Sf);
            *reinterpret_cast<float4*>(L + e4 * 4) = p;
        }
        __syncthreads();
    }
}

// ---------------- K3b: XLA-GPU two-stage column reduction replica (DO NOT TOUCH) ----------------
__global__ __launch_bounds__(1024) void colsum_kernel() {
    __shared__ float part[32][33];
    const int b  = blockIdx.y;
    const int m  = blockIdx.x * 32 + threadIdx.x;
    const int ty = threadIdx.y;
    const float* A = g_att + (size_t)b * NSEQ * NSEQ + m;

    float s[8];
#pragma unroll
    for (int p = 0; p < 8; p++) {
        float acc = 0.f;
#pragma unroll
        for (int k = 0; k < 32; k++)
            acc += A[(size_t)(p * 1024 + ty + 32 * k) * NSEQ];
        s[p] = acc;
    }

    float s1[8];
#pragma unroll
    for (int p = 0; p < 8; p++) {
        __syncthreads();
        part[ty][threadIdx.x] = s[p];
        __syncthreads();
        float q = part[threadIdx.x][ty];
#pragma unroll
        for (int off = 16; off; off >>= 1)
            q += __shfl_down_sync(0xffffffffu, q, off);
        s1[p] = q;
    }

    if (threadIdx.x == 0) {
        float r = ((s1[0] + s1[4]) + (s1[2] + s1[6]))
                + ((s1[1] + s1[5]) + (s1[3] + s1[7]));
        g_sel[b * NSEQ + blockIdx.x * 32 + ty] = r;
    }
}

// ---------------- K4: top-k (bitonic sort, desc value / asc index tie-break) ----------------
#define K4_SMEM (NSEQ * 8)
__global__ __launch_bounds__(1024) void topk_kernel() {
    extern __shared__ unsigned long long keys[];
    const int b = blockIdx.x;
    const int tid = threadIdx.x;

    for (int e = tid; e < NSEQ; e += 1024) {
        unsigned int u = __float_as_uint(g_sel[b * NSEQ + e]);
        u = (u & 0x80000000u) ? ~u : (u | 0x80000000u);
        u = ~u;
        keys[e] = ((unsigned long long)u << 32) | (unsigned int)e;
    }
    __syncthreads();

    for (int size = 2; size <= NSEQ; size <<= 1) {
        for (int stride = size >> 1; stride > 0; stride >>= 1) {
            for (int i = tid; i < NSEQ; i += 1024) {
                int j = i ^ stride;
                if (j > i) {
                    bool up = ((i & size) == 0);
                    unsigned long long a = keys[i], c = keys[j];
                    if ((a > c) == up) { keys[i] = c; keys[j] = a; }
                }
            }
            __syncthreads();
        }
    }

    for (int e = tid; e < MSEL; e += 1024)
        g_idx[b * MSEL + e] = (int)(keys[e] & 0xffffffffu);
}

// ---------------- K5: gather + scores @ v^T, K-split x4 ----------------
#define VS_STRIDE 68
__global__ __launch_bounds__(256) void out_kernel() {
    __shared__ float Vs[32 * VS_STRIDE];
    __shared__ float Ps[64][36];
    __shared__ int   srow[64];

    const int z  = blockIdx.z;           // b*4 + ksplit
    const int b  = z >> 2;
    const int ks = z & 3;
    const int c0 = blockIdx.y * 64;
    const int j0 = blockIdx.x * 64;
    const int tid = threadIdx.x;
    const int tx = tid & 15, ty = tid >> 4;

    if (tid < 64) srow[tid] = g_idx[b * MSEL + j0 + tid];
    __syncthreads();

    unsigned long long acc2[2][4];
#pragma unroll
    for (int i = 0; i < 2; i++)
#pragma unroll
        for (int j = 0; j < 4; j++) acc2[i][j] = 0ull;

    const float* vb = g_v + ((size_t)b * CCH + c0) * NSEQ;
    const float* Ab = g_att + (size_t)b * NSEQ * NSEQ;

    const int kbeg = ks * (NSEQ / 4), kend = kbeg + NSEQ / 4;
    for (int k0 = kbeg; k0 < kend; k0 += 32) {
#pragma unroll
        for (int e4 = tid; e4 < 512; e4 += 256) {
            int r = e4 >> 3, k4 = e4 & 7;
            float4 v = *reinterpret_cast<const float4*>(vb + (size_t)r * NSEQ + k0 + k4 * 4);
            float* vp = Vs + (r & 31) * VS_STRIDE + (r >> 5);
            vp[(k4 * 4 + 0) * 2] = v.x; vp[(k4 * 4 + 1) * 2] = v.y;
            vp[(k4 * 4 + 2) * 2] = v.z; vp[(k4 * 4 + 3) * 2] = v.w;
            float4 l = *reinterpret_cast<const float4*>(Ab + (size_t)srow[r] * NSEQ + k0 + k4 * 4);
            *reinterpret_cast<float4*>(&Ps[r][k4 * 4]) = l;
        }
        __syncthreads();
#pragma unroll
        for (int k = 0; k < 32; k += 4) {
            float4 av[2][2];
#pragma unroll
            for (int i2 = 0; i2 < 2; i2++) {
                const float4* vp = reinterpret_cast<const float4*>(Vs + (ty + 16 * i2) * VS_STRIDE + 2 * k);
                av[i2][0] = vp[0];
                av[i2][1] = vp[1];
            }
#pragma unroll
            for (int j = 0; j < 4; j++) {
                float4 pv = *reinterpret_cast<float4*>(&Ps[tx + 16 * j][k]);
                unsigned long long p0 = pack2(pv.x, pv.x);
                unsigned long long p1 = pack2(pv.y, pv.y);
                unsigned long long p2 = pack2(pv.z, pv.z);
                unsigned long long p3 = pack2(pv.w, pv.w);
#pragma unroll
                for (int i2 = 0; i2 < 2; i2++) {
                    const unsigned long long* a = reinterpret_cast<const unsigned long long*>(&av[i2][0]);
                    fma2(acc2[i2][j], a[0], p0);
                    fma2(acc2[i2][j], a[1], p1);
                    fma2(acc2[i2][j], a[2], p2);
                    fma2(acc2[i2][j], a[3], p3);
                }
            }
        }
        __syncthreads();
    }

    float* op = g_opart + (size_t)z * CCH * MSEL;
#pragma unroll
    for (int i2 = 0; i2 < 2; i2++)
#pragma unroll
        for (int j = 0; j < 4; j++) {
            float lo, hi;
            unpack2(acc2[i2][j], lo, hi);
            op[(size_t)(c0 + ty + 16 * i2)      * MSEL + j0 + tx + 16 * j] = lo;
            op[(size_t)(c0 + ty + 16 * i2 + 32) * MSEL + j0 + tx + 16 * j] = hi;
        }
}

// ---------------- K5b: combine K-split partials ----------------
__global__ __launch_bounds__(256) void combine_kernel(float* __restrict__ out) {
    const int b = blockIdx.y;
    const size_t e4 = (size_t)blockIdx.x * 256 + threadIdx.x;
    const float* p0 = g_opart + (size_t)(b * 4 + 0) * CCH * MSEL;
    const float* p1 = g_opart + (size_t)(b * 4 + 1) * CCH * MSEL;
    const float* p2 = g_opart + (size_t)(b * 4 + 2) * CCH * MSEL;
    const float* p3 = g_opart + (size_t)(b * 4 + 3) * CCH * MSEL;
    float4 a = reinterpret_cast<const float4*>(p0)[e4];
    float4 c = reinterpret_cast<const float4*>(p1)[e4];
    float4 d = reinterpret_cast<const float4*>(p2)[e4];
    float4 f = reinterpret_cast<const float4*>(p3)[e4];
    float4 r;
    r.x = ((a.x + c.x) + d.x) + f.x;
    r.y = ((a.y + c.y) + d.y) + f.y;
    r.z = ((a.z + c.z) + d.z) + f.z;
    r.w = ((a.w + c.w) + d.w) + f.w;
    reinterpret_cast<float4*>(out + (size_t)b * CCH * MSEL)[e4] = r;
}

// ---------------- launch ----------------
extern "C" void kernel_launch(void* const* d_in, const int* in_sizes, int n_in,
                              void* d_out, int out_size) {
    const float* x  = (const float*)d_in[0];
    const float* Wq = (const float*)d_in[1];
    const float* Wk = (const float*)d_in[2];
    const float* Wv = (const float*)d_in[3];
    float* out = (float*)d_out;

    cudaFuncSetAttribute(energy_kernel, cudaFuncAttributeMaxDynamicSharedMemorySize, K2_SMEM);
    cudaFuncSetAttribute(topk_kernel,   cudaFuncAttributeMaxDynamicSharedMemorySize, K4_SMEM);

    qkv_kernel<<<dim3(NSEQ / 64, BATCH), 256>>>(x, Wq, Wk, Wv);
    energy_kernel<<<dim3(NSEQ / 128, NSEQ / 256, BATCH), 512, K2_SMEM>>>();
    dummy_kernel<<<1, 32>>>();   // puts softmax_kernel in the ncu capture slot (#6)
    softmax_kernel<<<dim3(256, BATCH), 256>>>();
    colsum_kernel<<<dim3(NSEQ / 32, BATCH), dim3(32, 32)>>>();
    topk_kernel<<<BATCH, 1024, K4_SMEM>>>();
    out_kernel<<<dim3(MSEL / 64, CCH / 64, BATCH * 4), 256>>>();
    combine_kernel<<<dim3(CCH * MSEL / 4 / 256, BATCH), 256>>>(out);
}